// round 2
// baseline (speedup 1.0000x reference)
#include <cuda_runtime.h>

#define NB 2
#define SS 2048
#define DD 1024
#define NH 16
#define HD 64
#define MM (NB*SS)

// Scratch (allocation-free rule: __device__ globals)
__device__ float g_q[NB*NH*SS*HD];
__device__ float g_k[NB*NH*SS*HD];
__device__ float g_v[NB*NH*SS*HD];
__device__ float g_z[NB*SS*DD];

// ---------------------------------------------------------------------------
// SGEMM: C[M,N] = A[M,K] * W[K,N] ; M=4096, N=K=1024
// BM=128, BN=128, BK=16, 256 threads, 8x8 microtile
// DST: 0->g_q, 1->g_k, 2->g_v (split-head layout), 3->Cout (+bias)
// SRC_Z: 1 -> read A from g_z
// ---------------------------------------------------------------------------
#define BM 128
#define BN 128
#define BK 16

template<int SRC_Z, int DST>
__global__ __launch_bounds__(256, 2)
void sgemm_kernel(const float* __restrict__ Ain, const float* __restrict__ W,
                  const float* __restrict__ bias, float* __restrict__ Cout)
{
    __shared__ float As[BK][BM + 4];
    __shared__ float Bs[BK][BN + 4];
    const int tid = threadIdx.x;
    const int bx = blockIdx.x, by = blockIdx.y;
    const int tm = (tid >> 4) << 3;   // 0..120
    const int tn = (tid & 15) << 3;   // 0..120

    const float* A = SRC_Z ? g_z : Ain;
    const float* Ablk = A + (size_t)by * BM * DD;
    const float* Wblk = W + bx * BN;

    float acc[8][8];
#pragma unroll
    for (int i = 0; i < 8; i++)
#pragma unroll
        for (int j = 0; j < 8; j++) acc[i][j] = 0.f;

    for (int kt = 0; kt < DD; kt += BK) {
        // Load A tile (transposed into As[k][m])
#pragma unroll
        for (int i = 0; i < 2; i++) {
            int idx = tid + i * 256;          // 0..511 float4s
            int m = idx >> 2, q = idx & 3;
            float4 v = *(const float4*)(Ablk + m * DD + kt + q * 4);
            As[q*4+0][m] = v.x; As[q*4+1][m] = v.y;
            As[q*4+2][m] = v.z; As[q*4+3][m] = v.w;
        }
        // Load B tile
#pragma unroll
        for (int i = 0; i < 2; i++) {
            int idx = tid + i * 256;
            int k = idx >> 5, nq = idx & 31;
            *(float4*)&Bs[k][nq * 4] = *(const float4*)(Wblk + (kt + k) * DD + nq * 4);
        }
        __syncthreads();
#pragma unroll
        for (int k = 0; k < BK; k++) {
            float a[8], b[8];
            float4 t;
            t = *(const float4*)&As[k][tm];     a[0]=t.x; a[1]=t.y; a[2]=t.z; a[3]=t.w;
            t = *(const float4*)&As[k][tm+4];   a[4]=t.x; a[5]=t.y; a[6]=t.z; a[7]=t.w;
            t = *(const float4*)&Bs[k][tn];     b[0]=t.x; b[1]=t.y; b[2]=t.z; b[3]=t.w;
            t = *(const float4*)&Bs[k][tn+4];   b[4]=t.x; b[5]=t.y; b[6]=t.z; b[7]=t.w;
#pragma unroll
            for (int i = 0; i < 8; i++)
#pragma unroll
                for (int j = 0; j < 8; j++)
                    acc[i][j] = fmaf(a[i], b[j], acc[i][j]);
        }
        __syncthreads();
    }

    const int n0 = bx * BN + tn;
    if (DST < 3) {
        // Write into [B, H, S, HD] layout
        float* dst = (DST == 0) ? g_q : (DST == 1) ? g_k : g_v;
        const int h = n0 >> 6, hd = n0 & 63;   // tn mult of 8 -> 8 cols same head
#pragma unroll
        for (int i = 0; i < 8; i++) {
            int m = by * BM + tm + i;
            int b = m >> 11, s = m & (SS - 1);
            float* p = dst + (((size_t)(b * NH + h) * SS + s) * HD + hd);
            *(float4*)p       = make_float4(acc[i][0], acc[i][1], acc[i][2], acc[i][3]);
            *(float4*)(p + 4) = make_float4(acc[i][4], acc[i][5], acc[i][6], acc[i][7]);
        }
    } else {
        float4 b0 = *(const float4*)(bias + n0);
        float4 b1 = *(const float4*)(bias + n0 + 4);
#pragma unroll
        for (int i = 0; i < 8; i++) {
            int m = by * BM + tm + i;
            float* p = Cout + (size_t)m * DD + n0;
            *(float4*)p       = make_float4(acc[i][0]+b0.x, acc[i][1]+b0.y, acc[i][2]+b0.z, acc[i][3]+b0.w);
            *(float4*)(p + 4) = make_float4(acc[i][4]+b1.x, acc[i][5]+b1.y, acc[i][6]+b1.z, acc[i][7]+b1.w);
        }
    }
}

// ---------------------------------------------------------------------------
// Flash attention: per (qb, bh) block, 64 q-rows x head. 128 threads.
// Online softmax; causal: iterate kt <= qb only.
// Smem chunk swizzle: chunk' = c4 ^ (r>>3) -> conflict-free K-row reads.
// ---------------------------------------------------------------------------
#define BQ 64
#define BKV 64
#define SW(r, c4) ((((c4) ^ ((r) >> 3)) & 15))

__global__ __launch_bounds__(128)
void flash_kernel()
{
    __shared__ float Qs[BQ][HD];
    __shared__ float KVs[BKV][HD];
    __shared__ float Ps[BQ][BKV];

    const int tid = threadIdx.x;
    const int qb = blockIdx.x;
    const int bh = blockIdx.y;
    const int ty = tid >> 3;      // 0..15 (row group)
    const int tx = tid & 7;       // 0..7  (col group)
    const int r0 = ty * 4;

    const float* Qg = g_q + ((size_t)bh * SS + qb * BQ) * HD;
    const float* Kg = g_k + (size_t)bh * SS * HD;
    const float* Vg = g_v + (size_t)bh * SS * HD;

    // Load Q tile (swizzled)
#pragma unroll
    for (int i = 0; i < 8; i++) {
        int idx = tid + i * 128;                 // 0..1023 float4s
        int r = idx >> 4, c4 = idx & 15;
        *(float4*)&Qs[r][SW(r, c4) * 4] = *(const float4*)(Qg + r * HD + c4 * 4);
    }

    float O[4][8];
    float mrow[4], lrow[4];
#pragma unroll
    for (int i = 0; i < 4; i++) {
        mrow[i] = -1e30f; lrow[i] = 0.f;
#pragma unroll
        for (int j = 0; j < 8; j++) O[i][j] = 0.f;
    }

    const float scale = 0.125f;   // 1/sqrt(64)

    for (int kt = 0; kt <= qb; ++kt) {
        __syncthreads();    // prev-iter PV reads of KVs/Ps done
        // Load K tile
#pragma unroll
        for (int i = 0; i < 8; i++) {
            int idx = tid + i * 128;
            int r = idx >> 4, c4 = idx & 15;
            *(float4*)&KVs[r][SW(r, c4) * 4] = *(const float4*)(Kg + (kt * BKV + r) * HD + c4 * 4);
        }
        __syncthreads();

        // S = Q K^T  (each thread: 4 rows x 8 cols)
        float s[4][8];
#pragma unroll
        for (int i = 0; i < 4; i++)
#pragma unroll
            for (int j = 0; j < 8; j++) s[i][j] = 0.f;

#pragma unroll 4
        for (int d = 0; d < HD; d += 4) {
            int c4 = d >> 2;
            float4 qa[4], kb[8];
#pragma unroll
            for (int i = 0; i < 4; i++) qa[i] = *(const float4*)&Qs[r0 + i][SW(r0 + i, c4) * 4];
#pragma unroll
            for (int j = 0; j < 8; j++) kb[j] = *(const float4*)&KVs[tx * 8 + j][SW(tx * 8 + j, c4) * 4];
#pragma unroll
            for (int i = 0; i < 4; i++)
#pragma unroll
                for (int j = 0; j < 8; j++) {
                    s[i][j] = fmaf(qa[i].x, kb[j].x, s[i][j]);
                    s[i][j] = fmaf(qa[i].y, kb[j].y, s[i][j]);
                    s[i][j] = fmaf(qa[i].z, kb[j].z, s[i][j]);
                    s[i][j] = fmaf(qa[i].w, kb[j].w, s[i][j]);
                }
        }

        // Scale + causal mask (diag tile only)
        const bool diag = (kt == qb);
#pragma unroll
        for (int i = 0; i < 4; i++) {
            int r = r0 + i;
#pragma unroll
            for (int j = 0; j < 8; j++) {
                float v = s[i][j] * scale;
                if (diag && (tx * 8 + j) > r) v = -1e30f;
                s[i][j] = v;
            }
        }

        // Online softmax (row state replicated across the 8 tx lanes)
#pragma unroll
        for (int i = 0; i < 4; i++) {
            float mx = s[i][0];
#pragma unroll
            for (int j = 1; j < 8; j++) mx = fmaxf(mx, s[i][j]);
            mx = fmaxf(mx, __shfl_xor_sync(0xffffffffu, mx, 1));
            mx = fmaxf(mx, __shfl_xor_sync(0xffffffffu, mx, 2));
            mx = fmaxf(mx, __shfl_xor_sync(0xffffffffu, mx, 4));
            float mnew = fmaxf(mrow[i], mx);
            float corr = __expf(mrow[i] - mnew);
            mrow[i] = mnew;
            float rs = 0.f;
#pragma unroll
            for (int j = 0; j < 8; j++) { float p = __expf(s[i][j] - mnew); s[i][j] = p; rs += p; }
            rs += __shfl_xor_sync(0xffffffffu, rs, 1);
            rs += __shfl_xor_sync(0xffffffffu, rs, 2);
            rs += __shfl_xor_sync(0xffffffffu, rs, 4);
            lrow[i] = lrow[i] * corr + rs;
#pragma unroll
            for (int j = 0; j < 8; j++) O[i][j] *= corr;
            *(float4*)&Ps[r0 + i][tx * 8]     = make_float4(s[i][0], s[i][1], s[i][2], s[i][3]);
            *(float4*)&Ps[r0 + i][tx * 8 + 4] = make_float4(s[i][4], s[i][5], s[i][6], s[i][7]);
        }
        __syncthreads();   // everyone done reading K & writing Ps

        // Load V tile into KVs
#pragma unroll
        for (int i = 0; i < 8; i++) {
            int idx = tid + i * 128;
            int r = idx >> 4, c4 = idx & 15;
            *(float4*)&KVs[r][SW(r, c4) * 4] = *(const float4*)(Vg + (kt * BKV + r) * HD + c4 * 4);
        }
        __syncthreads();

        // O += P @ V  (thread owns rows r0..r0+3, d-cols tx*8..+7)
#pragma unroll 8
        for (int c = 0; c < BKV; c++) {
            float4 v0 = *(const float4*)&KVs[c][SW(c, 2 * tx) * 4];
            float4 v1 = *(const float4*)&KVs[c][SW(c, 2 * tx + 1) * 4];
#pragma unroll
            for (int i = 0; i < 4; i++) {
                float p = Ps[r0 + i][c];
                O[i][0] = fmaf(p, v0.x, O[i][0]);
                O[i][1] = fmaf(p, v0.y, O[i][1]);
                O[i][2] = fmaf(p, v0.z, O[i][2]);
                O[i][3] = fmaf(p, v0.w, O[i][3]);
                O[i][4] = fmaf(p, v1.x, O[i][4]);
                O[i][5] = fmaf(p, v1.y, O[i][5]);
                O[i][6] = fmaf(p, v1.z, O[i][6]);
                O[i][7] = fmaf(p, v1.w, O[i][7]);
            }
        }
    }

    // Epilogue: normalize and write z in [B, S, D] layout
    const int b = bh >> 4, h = bh & 15;
#pragma unroll
    for (int i = 0; i < 4; i++) {
        float inv = 1.f / lrow[i];
        int srow = qb * BQ + r0 + i;
        float* zp = g_z + ((size_t)(b * SS + srow)) * DD + h * HD + tx * 8;
        *(float4*)zp       = make_float4(O[i][0]*inv, O[i][1]*inv, O[i][2]*inv, O[i][3]*inv);
        *(float4*)(zp + 4) = make_float4(O[i][4]*inv, O[i][5]*inv, O[i][6]*inv, O[i][7]*inv);
    }
}

// ---------------------------------------------------------------------------
extern "C" void kernel_launch(void* const* d_in, const int* in_sizes, int n_in,
                              void* d_out, int out_size)
{
    const float* x  = (const float*)d_in[0];
    const float* Wq = (const float*)d_in[1];
    const float* Wk = (const float*)d_in[2];
    const float* Wv = (const float*)d_in[3];
    const float* Wo = (const float*)d_in[4];
    const float* bo = (const float*)d_in[5];
    float* out = (float*)d_out;

    dim3 gg(DD / BN, MM / BM);           // (8, 32)
    sgemm_kernel<0, 0><<<gg, 256>>>(x, Wq, nullptr, nullptr);
    sgemm_kernel<0, 1><<<gg, 256>>>(x, Wk, nullptr, nullptr);
    sgemm_kernel<0, 2><<<gg, 256>>>(x, Wv, nullptr, nullptr);

    dim3 ga(SS / BQ, NB * NH);           // (32, 32)
    flash_kernel<<<ga, 128>>>();

    sgemm_kernel<1, 3><<<gg, 256>>>(nullptr, Wo, bo, out);
}

// round 4
// speedup vs baseline: 1.2977x; 1.2977x over previous
#include <cuda_runtime.h>
#include <cuda_bf16.h>
#include <cstdint>

#define NB 2
#define SS 2048
#define DD 1024
#define NH 16
#define HD 64
#define MM (NB*SS)
#define KTOT 3072   // 3x K-expansion for bf16 hi/lo compensation

// ---------------------------------------------------------------------------
// Scratch (__device__ globals; allocation-free rule)
// ---------------------------------------------------------------------------
__device__ float g_q[(size_t)NB*NH*SS*HD];
__device__ float g_k[(size_t)NB*NH*SS*HD];
__device__ float g_v[(size_t)NB*NH*SS*HD];
__device__ float g_z[(size_t)NB*SS*DD];
__device__ __nv_bfloat16 g_xs[(size_t)MM*KTOT];      // x split-expanded [M][3K]
__device__ __nv_bfloat16 g_zs[(size_t)MM*KTOT];      // z split-expanded [M][3K]
__device__ __nv_bfloat16 g_ws[4][(size_t)DD*KTOT];   // W transposed+split [N][3K]

// ---------------------------------------------------------------------------
// PTX helpers (sm_100-safe: cp.async / ldmatrix / mma.sync only)
// ---------------------------------------------------------------------------
__device__ __forceinline__ uint32_t smem_u32(const void* p) {
    uint32_t a;
    asm("{ .reg .u64 t; cvta.to.shared.u64 t, %1; cvt.u32.u64 %0, t; }" : "=r"(a) : "l"(p));
    return a;
}
__device__ __forceinline__ void cp16(uint32_t s, const void* g) {
    asm volatile("cp.async.cg.shared.global [%0], [%1], 16;" :: "r"(s), "l"(g));
}
__device__ __forceinline__ void ldsm_x4(uint32_t (&r)[4], uint32_t a) {
    asm volatile("ldmatrix.sync.aligned.m8n8.x4.shared.b16 {%0,%1,%2,%3}, [%4];"
                 : "=r"(r[0]), "=r"(r[1]), "=r"(r[2]), "=r"(r[3]) : "r"(a));
}
__device__ __forceinline__ void ldsm_x2(uint32_t (&r)[2], uint32_t a) {
    asm volatile("ldmatrix.sync.aligned.m8n8.x2.shared.b16 {%0,%1}, [%2];"
                 : "=r"(r[0]), "=r"(r[1]) : "r"(a));
}
__device__ __forceinline__ void mma16816(float (&c)[4], const uint32_t (&a)[4],
                                         const uint32_t (&b)[2]) {
    asm volatile("mma.sync.aligned.m16n8k16.row.col.f32.bf16.bf16.f32 "
                 "{%0,%1,%2,%3}, {%4,%5,%6,%7}, {%8,%9}, {%0,%1,%2,%3};"
                 : "+f"(c[0]), "+f"(c[1]), "+f"(c[2]), "+f"(c[3])
                 : "r"(a[0]), "r"(a[1]), "r"(a[2]), "r"(a[3]), "r"(b[0]), "r"(b[1]));
}

// ---------------------------------------------------------------------------
// Conversion kernels
// ---------------------------------------------------------------------------
template<int MODE>
__global__ void conv_split(const float* __restrict__ xin) {
    const float* in = (MODE == 0) ? xin : g_z;
    __nv_bfloat16* out = (MODE == 0) ? g_xs : g_zs;
    size_t idx = (size_t)blockIdx.x * 256 + threadIdx.x;
    int m = (int)(idx >> 10), kk = (int)(idx & 1023);
    float v = in[idx];
    __nv_bfloat16 hi = __float2bfloat16(v);
    __nv_bfloat16 lo = __float2bfloat16(v - __bfloat162float(hi));
    __nv_bfloat16* row = out + (size_t)m * KTOT;
    row[kk] = hi; row[1024 + kk] = hi; row[2048 + kk] = lo;
}

// W[K,N] -> g_ws[z][N][3K]: seg0 = hi, seg1 = lo, seg2 = hi
// (pairs with activation rows: seg0 = hi, seg1 = hi, seg2 = lo)
__global__ void conv_w(const float* __restrict__ W0, const float* __restrict__ W1,
                       const float* __restrict__ W2, const float* __restrict__ W3) {
    __shared__ float t[32][33];
    const int z = blockIdx.z;
    const float* W = (z == 0) ? W0 : (z == 1) ? W1 : (z == 2) ? W2 : W3;
    __nv_bfloat16* O = g_ws[z];
    int tx = threadIdx.x, ty = threadIdx.y;
    int k0 = blockIdx.y * 32, n0 = blockIdx.x * 32;
#pragma unroll
    for (int i = 0; i < 4; i++) {
        int kk = ty * 4 + i;
        t[kk][tx] = W[(size_t)(k0 + kk) * DD + n0 + tx];
    }
    __syncthreads();
#pragma unroll
    for (int i = 0; i < 4; i++) {
        int n = n0 + ty * 4 + i;
        int k = k0 + tx;
        float v = t[tx][ty * 4 + i];
        __nv_bfloat16 hi = __float2bfloat16(v);
        __nv_bfloat16 lo = __float2bfloat16(v - __bfloat162float(hi));
        __nv_bfloat16* row = O + (size_t)n * KTOT;
        row[k] = hi; row[2048 + k] = hi; row[1024 + k] = lo;
    }
}

// ---------------------------------------------------------------------------
// mma.sync bf16 GEMM: C[4096,1024] over K=3072.
// 128x128 CTA tile, 8 warps (2x4), warp tile 64x32, BK=32, cp.async 2-stage.
// Smem rows padded to 40 bf16 (80 B) -> conflict-free ldmatrix.
// MODE 0: A=g_xs, B=g_ws[blockIdx.z], dst split-head g_q/g_k/g_v
// MODE 1: A=g_zs, B=g_ws[3], dst = Cout + bias
// ---------------------------------------------------------------------------
#define GBK 32
#define NCH (KTOT / GBK)   // 96
#define PAD 40

template<int MODE>
__global__ __launch_bounds__(256)
void mma_gemm(const float* __restrict__ bias, float* __restrict__ Cout) {
    __shared__ __align__(16) __nv_bfloat16 sA[2][128][PAD];
    __shared__ __align__(16) __nv_bfloat16 sB[2][128][PAD];

    const int tid = threadIdx.x;
    const int wid = tid >> 5, lane = tid & 31;
    const int wm = wid >> 2;          // 0..1  -> m offset wm*64
    const int wn = wid & 3;           // 0..3  -> n offset wn*32

    const __nv_bfloat16* A = (MODE == 0) ? g_xs : g_zs;
    const __nv_bfloat16* B = (MODE == 0) ? g_ws[blockIdx.z] : g_ws[3];
    const __nv_bfloat16* Ab = A + (size_t)blockIdx.y * 128 * KTOT;
    const __nv_bfloat16* Bb = B + (size_t)blockIdx.x * 128 * KTOT;

    const uint32_t sAu = smem_u32(&sA[0][0][0]);
    const uint32_t sBu = smem_u32(&sB[0][0][0]);
    const uint32_t stageB = 128 * PAD * 2;   // bytes per stage

    // Per-thread load mapping: idx = tid + j*256 (0..511); r = idx>>2, c = idx&3
    const int lr0 = tid >> 2, lc = (tid & 3) * 8;
    const int lr1 = (tid + 256) >> 2;

    float acc[4][4][4];
#pragma unroll
    for (int i = 0; i < 4; i++)
#pragma unroll
        for (int j = 0; j < 4; j++)
#pragma unroll
            for (int v = 0; v < 4; v++) acc[i][j][v] = 0.f;

    auto load_chunk = [&](int chunk, int s) {
        const __nv_bfloat16* Ak = Ab + (size_t)chunk * GBK;
        const __nv_bfloat16* Bk = Bb + (size_t)chunk * GBK;
        uint32_t dA0 = sAu + s * stageB + (lr0 * PAD + lc) * 2;
        uint32_t dA1 = sAu + s * stageB + (lr1 * PAD + lc) * 2;
        uint32_t dB0 = sBu + s * stageB + (lr0 * PAD + lc) * 2;
        uint32_t dB1 = sBu + s * stageB + (lr1 * PAD + lc) * 2;
        cp16(dA0, Ak + (size_t)lr0 * KTOT + lc);
        cp16(dA1, Ak + (size_t)lr1 * KTOT + lc);
        cp16(dB0, Bk + (size_t)lr0 * KTOT + lc);
        cp16(dB1, Bk + (size_t)lr1 * KTOT + lc);
    };

    load_chunk(0, 0);
    asm volatile("cp.async.commit_group;");

    for (int i = 0; i < NCH; i++) {
        const int s = i & 1;
        if (i + 1 < NCH) {
            load_chunk(i + 1, (i + 1) & 1);
            asm volatile("cp.async.commit_group;");
            asm volatile("cp.async.wait_group 1;");
        } else {
            asm volatile("cp.async.wait_group 0;");
        }
        __syncthreads();

#pragma unroll
        for (int k0 = 0; k0 < GBK; k0 += 16) {
            uint32_t afr[4][4];
#pragma unroll
            for (int mi = 0; mi < 4; mi++) {
                int row = wm * 64 + mi * 16 + (lane & 15);
                int col = k0 + (lane >> 4) * 8;
                ldsm_x4(afr[mi], sAu + s * stageB + (row * PAD + col) * 2);
            }
            uint32_t bfr[4][2];
#pragma unroll
            for (int ni = 0; ni < 4; ni++) {
                int l = lane & 15;
                int row = wn * 32 + ni * 8 + (l & 7);
                int col = k0 + (l >> 3) * 8;
                ldsm_x2(bfr[ni], sBu + s * stageB + (row * PAD + col) * 2);
            }
#pragma unroll
            for (int mi = 0; mi < 4; mi++)
#pragma unroll
                for (int ni = 0; ni < 4; ni++)
                    mma16816(acc[mi][ni], afr[mi], bfr[ni]);
        }
        __syncthreads();
    }

    // Epilogue
    const int qr = lane >> 2, qc = (lane & 3) * 2;
#pragma unroll
    for (int mi = 0; mi < 4; mi++) {
#pragma unroll
        for (int ni = 0; ni < 4; ni++) {
            int col = blockIdx.x * 128 + wn * 32 + ni * 8 + qc;
            int row0 = blockIdx.y * 128 + wm * 64 + mi * 16 + qr;
            int row1 = row0 + 8;
            if (MODE == 0) {
                float* dst = (blockIdx.z == 0) ? g_q : (blockIdx.z == 1) ? g_k : g_v;
                int h = col >> 6, hd = col & 63;
                int b0 = row0 >> 11, s0 = row0 & (SS - 1);
                int b1 = row1 >> 11, s1 = row1 & (SS - 1);
                float2* p0 = (float2*)(dst + (((size_t)(b0 * NH + h) * SS + s0) * HD + hd));
                float2* p1 = (float2*)(dst + (((size_t)(b1 * NH + h) * SS + s1) * HD + hd));
                *p0 = make_float2(acc[mi][ni][0], acc[mi][ni][1]);
                *p1 = make_float2(acc[mi][ni][2], acc[mi][ni][3]);
            } else {
                float bx0 = bias[col], bx1 = bias[col + 1];
                float2* p0 = (float2*)(Cout + (size_t)row0 * DD + col);
                float2* p1 = (float2*)(Cout + (size_t)row1 * DD + col);
                *p0 = make_float2(acc[mi][ni][0] + bx0, acc[mi][ni][1] + bx1);
                *p1 = make_float2(acc[mi][ni][2] + bx0, acc[mi][ni][3] + bx1);
            }
        }
    }
}

// ---------------------------------------------------------------------------
// Flash attention (unchanged from baseline)
// ---------------------------------------------------------------------------
#define BQ 64
#define BKV 64
#define SW(r, c4) ((((c4) ^ ((r) >> 3)) & 15))

__global__ __launch_bounds__(128)
void flash_kernel()
{
    __shared__ float Qs[BQ][HD];
    __shared__ float KVs[BKV][HD];
    __shared__ float Ps[BQ][BKV];

    const int tid = threadIdx.x;
    const int qb = blockIdx.x;
    const int bh = blockIdx.y;
    const int ty = tid >> 3;
    const int tx = tid & 7;
    const int r0 = ty * 4;

    const float* Qg = g_q + ((size_t)bh * SS + qb * BQ) * HD;
    const float* Kg = g_k + (size_t)bh * SS * HD;
    const float* Vg = g_v + (size_t)bh * SS * HD;

#pragma unroll
    for (int i = 0; i < 8; i++) {
        int idx = tid + i * 128;
        int r = idx >> 4, c4 = idx & 15;
        *(float4*)&Qs[r][SW(r, c4) * 4] = *(const float4*)(Qg + r * HD + c4 * 4);
    }

    float O[4][8];
    float mrow[4], lrow[4];
#pragma unroll
    for (int i = 0; i < 4; i++) {
        mrow[i] = -1e30f; lrow[i] = 0.f;
#pragma unroll
        for (int j = 0; j < 8; j++) O[i][j] = 0.f;
    }

    const float scale = 0.125f;

    for (int kt = 0; kt <= qb; ++kt) {
        __syncthreads();
#pragma unroll
        for (int i = 0; i < 8; i++) {
            int idx = tid + i * 128;
            int r = idx >> 4, c4 = idx & 15;
            *(float4*)&KVs[r][SW(r, c4) * 4] = *(const float4*)(Kg + (kt * BKV + r) * HD + c4 * 4);
        }
        __syncthreads();

        float s[4][8];
#pragma unroll
        for (int i = 0; i < 4; i++)
#pragma unroll
            for (int j = 0; j < 8; j++) s[i][j] = 0.f;

#pragma unroll 4
        for (int d = 0; d < HD; d += 4) {
            int c4 = d >> 2;
            float4 qa[4], kb[8];
#pragma unroll
            for (int i = 0; i < 4; i++) qa[i] = *(const float4*)&Qs[r0 + i][SW(r0 + i, c4) * 4];
#pragma unroll
            for (int j = 0; j < 8; j++) kb[j] = *(const float4*)&KVs[tx * 8 + j][SW(tx * 8 + j, c4) * 4];
#pragma unroll
            for (int i = 0; i < 4; i++)
#pragma unroll
                for (int j = 0; j < 8; j++) {
                    s[i][j] = fmaf(qa[i].x, kb[j].x, s[i][j]);
                    s[i][j] = fmaf(qa[i].y, kb[j].y, s[i][j]);
                    s[i][j] = fmaf(qa[i].z, kb[j].z, s[i][j]);
                    s[i][j] = fmaf(qa[i].w, kb[j].w, s[i][j]);
                }
        }

        const bool diag = (kt == qb);
#pragma unroll
        for (int i = 0; i < 4; i++) {
            int r = r0 + i;
#pragma unroll
            for (int j = 0; j < 8; j++) {
                float v = s[i][j] * scale;
                if (diag && (tx * 8 + j) > r) v = -1e30f;
                s[i][j] = v;
            }
        }

#pragma unroll
        for (int i = 0; i < 4; i++) {
            float mx = s[i][0];
#pragma unroll
            for (int j = 1; j < 8; j++) mx = fmaxf(mx, s[i][j]);
            mx = fmaxf(mx, __shfl_xor_sync(0xffffffffu, mx, 1));
            mx = fmaxf(mx, __shfl_xor_sync(0xffffffffu, mx, 2));
            mx = fmaxf(mx, __shfl_xor_sync(0xffffffffu, mx, 4));
            float mnew = fmaxf(mrow[i], mx);
            float corr = __expf(mrow[i] - mnew);
            mrow[i] = mnew;
            float rs = 0.f;
#pragma unroll
            for (int j = 0; j < 8; j++) { float p = __expf(s[i][j] - mnew); s[i][j] = p; rs += p; }
            rs += __shfl_xor_sync(0xffffffffu, rs, 1);
            rs += __shfl_xor_sync(0xffffffffu, rs, 2);
            rs += __shfl_xor_sync(0xffffffffu, rs, 4);
            lrow[i] = lrow[i] * corr + rs;
#pragma unroll
            for (int j = 0; j < 8; j++) O[i][j] *= corr;
            *(float4*)&Ps[r0 + i][tx * 8]     = make_float4(s[i][0], s[i][1], s[i][2], s[i][3]);
            *(float4*)&Ps[r0 + i][tx * 8 + 4] = make_float4(s[i][4], s[i][5], s[i][6], s[i][7]);
        }
        __syncthreads();

#pragma unroll
        for (int i = 0; i < 8; i++) {
            int idx = tid + i * 128;
            int r = idx >> 4, c4 = idx & 15;
            *(float4*)&KVs[r][SW(r, c4) * 4] = *(const float4*)(Vg + (kt * BKV + r) * HD + c4 * 4);
        }
        __syncthreads();

#pragma unroll 8
        for (int c = 0; c < BKV; c++) {
            float4 v0 = *(const float4*)&KVs[c][SW(c, 2 * tx) * 4];
            float4 v1 = *(const float4*)&KVs[c][SW(c, 2 * tx + 1) * 4];
#pragma unroll
            for (int i = 0; i < 4; i++) {
                float p = Ps[r0 + i][c];
                O[i][0] = fmaf(p, v0.x, O[i][0]);
                O[i][1] = fmaf(p, v0.y, O[i][1]);
                O[i][2] = fmaf(p, v0.z, O[i][2]);
                O[i][3] = fmaf(p, v0.w, O[i][3]);
                O[i][4] = fmaf(p, v1.x, O[i][4]);
                O[i][5] = fmaf(p, v1.y, O[i][5]);
                O[i][6] = fmaf(p, v1.z, O[i][6]);
                O[i][7] = fmaf(p, v1.w, O[i][7]);
            }
        }
    }

    const int b = bh >> 4, h = bh & 15;
#pragma unroll
    for (int i = 0; i < 4; i++) {
        float inv = 1.f / lrow[i];
        int srow = qb * BQ + r0 + i;
        float* zp = g_z + ((size_t)(b * SS + srow)) * DD + h * HD + tx * 8;
        *(float4*)zp       = make_float4(O[i][0]*inv, O[i][1]*inv, O[i][2]*inv, O[i][3]*inv);
        *(float4*)(zp + 4) = make_float4(O[i][4]*inv, O[i][5]*inv, O[i][6]*inv, O[i][7]*inv);
    }
}

// ---------------------------------------------------------------------------
extern "C" void kernel_launch(void* const* d_in, const int* in_sizes, int n_in,
                              void* d_out, int out_size)
{
    const float* x  = (const float*)d_in[0];
    const float* Wq = (const float*)d_in[1];
    const float* Wk = (const float*)d_in[2];
    const float* Wv = (const float*)d_in[3];
    const float* Wo = (const float*)d_in[4];
    const float* bo = (const float*)d_in[5];
    float* out = (float*)d_out;

    conv_split<0><<<(size_t)MM * DD / 256, 256>>>(x);
    conv_w<<<dim3(32, 32, 4), dim3(32, 8)>>>(Wq, Wk, Wv, Wo);

    mma_gemm<0><<<dim3(8, 32, 3), 256>>>(nullptr, nullptr);

    flash_kernel<<<dim3(SS / BQ, NB * NH), 128>>>();

    conv_split<1><<<(size_t)MM * DD / 256, 256>>>(nullptr);
    mma_gemm<1><<<dim3(8, 32, 1), 256>>>(bo, out);
}

// round 7
// speedup vs baseline: 2.1614x; 1.6656x over previous
#include <cuda_runtime.h>
#include <cuda_bf16.h>
#include <cstdint>

#define NB 2
#define SS 2048
#define DD 1024
#define NH 16
#define HD 64
#define MM (NB*SS)
#define KTOT 3072   // 3x K-expansion for bf16 hi/lo compensation

// ---------------------------------------------------------------------------
// Scratch (__device__ globals; allocation-free rule)
// ---------------------------------------------------------------------------
__device__ __nv_bfloat16 g_xs[(size_t)MM*KTOT];        // x split-expanded [M][3K]
__device__ __nv_bfloat16 g_zs[(size_t)MM*KTOT];        // z split-expanded [M][3K]
__device__ __nv_bfloat16 g_ws[4][(size_t)DD*KTOT];     // W transposed+split [N][3K]
__device__ __nv_bfloat16 g_qx[(size_t)NB*NH*SS*192];   // Q [bh][s][qh|qh|ql], pre-scaled 1/8
__device__ __nv_bfloat16 g_kx[(size_t)NB*NH*SS*192];   // K [bh][s][kh|kl|kh]
__device__ __nv_bfloat16 g_vx[(size_t)NB*NH*3*SS*HD];  // V [bh][vh rows | vl rows | vh rows][hd]

// ---------------------------------------------------------------------------
// Helpers (sm_100-safe PTX: cp.async / ldmatrix / mma.sync)
// ---------------------------------------------------------------------------
__device__ __forceinline__ uint32_t smem_u32(const void* p) {
    uint32_t a;
    asm("{ .reg .u64 t; cvta.to.shared.u64 t, %1; cvt.u32.u64 %0, t; }" : "=r"(a) : "l"(p));
    return a;
}
__device__ __forceinline__ void cp16(uint32_t s, const void* g) {
    asm volatile("cp.async.cg.shared.global [%0], [%1], 16;" :: "r"(s), "l"(g));
}
__device__ __forceinline__ void ldsm_x4(uint32_t (&r)[4], uint32_t a) {
    asm volatile("ldmatrix.sync.aligned.m8n8.x4.shared.b16 {%0,%1,%2,%3}, [%4];"
                 : "=r"(r[0]), "=r"(r[1]), "=r"(r[2]), "=r"(r[3]) : "r"(a));
}
__device__ __forceinline__ void ldsm_x4t(uint32_t (&r)[4], uint32_t a) {
    asm volatile("ldmatrix.sync.aligned.m8n8.x4.trans.shared.b16 {%0,%1,%2,%3}, [%4];"
                 : "=r"(r[0]), "=r"(r[1]), "=r"(r[2]), "=r"(r[3]) : "r"(a));
}
__device__ __forceinline__ void ldsm_x2(uint32_t (&r)[2], uint32_t a) {
    asm volatile("ldmatrix.sync.aligned.m8n8.x2.shared.b16 {%0,%1}, [%2];"
                 : "=r"(r[0]), "=r"(r[1]) : "r"(a));
}
__device__ __forceinline__ void mma_bf16(float (&c)[4], const uint32_t (&a)[4],
                                         uint32_t b0, uint32_t b1) {
    asm volatile("mma.sync.aligned.m16n8k16.row.col.f32.bf16.bf16.f32 "
                 "{%0,%1,%2,%3}, {%4,%5,%6,%7}, {%8,%9}, {%0,%1,%2,%3};"
                 : "+f"(c[0]), "+f"(c[1]), "+f"(c[2]), "+f"(c[3])
                 : "r"(a[0]), "r"(a[1]), "r"(a[2]), "r"(a[3]), "r"(b0), "r"(b1));
}
__device__ __forceinline__ uint32_t bfpack(float a, float b) {
    __nv_bfloat162 t = __floats2bfloat162_rn(a, b);
    return *reinterpret_cast<uint32_t*>(&t);
}
__device__ __forceinline__ float bfres(float a) {
    return a - __bfloat162float(__float2bfloat16(a));
}
// exp on the FMA/ALU pipes (no MUFU). Valid for x <= 0; flushes to ~0 below -87.
__device__ __forceinline__ float fexp(float x) {
    float y = x * 1.4426950408889634f;
    y = fmaxf(y, -126.0f);
    float t = y + 12582912.0f;            // round-to-nearest-int (magic)
    int   i = __float_as_int(t);
    float f = y - (t - 12582912.0f);      // frac in [-0.5, 0.5]
    float p = fmaf(f, 1.3333558146e-3f, 9.6181291076e-3f);
    p = fmaf(f, p, 5.5504108664e-2f);
    p = fmaf(f, p, 2.4022650696e-1f);
    p = fmaf(f, p, 6.9314718056e-1f);
    p = fmaf(f, p, 1.0f);
    return p * __int_as_float((i + 127) << 23);
}

// ---------------------------------------------------------------------------
// Conversions
// ---------------------------------------------------------------------------
__global__ void conv_split(const float* __restrict__ xin) {
    size_t idx = (size_t)blockIdx.x * 256 + threadIdx.x;
    int m = (int)(idx >> 10), kk = (int)(idx & 1023);
    float v = xin[idx];
    __nv_bfloat16 hi = __float2bfloat16(v);
    __nv_bfloat16 lo = __float2bfloat16(v - __bfloat162float(hi));
    __nv_bfloat16* row = g_xs + (size_t)m * KTOT;
    row[kk] = hi; row[1024 + kk] = hi; row[2048 + kk] = lo;
}

// W[K,N] -> g_ws[z][N][3K]: seg0 = hi, seg1 = lo, seg2 = hi
__global__ void conv_w(const float* __restrict__ W0, const float* __restrict__ W1,
                       const float* __restrict__ W2, const float* __restrict__ W3) {
    __shared__ float t[32][33];
    const int z = blockIdx.z;
    const float* W = (z == 0) ? W0 : (z == 1) ? W1 : (z == 2) ? W2 : W3;
    __nv_bfloat16* O = g_ws[z];
    int tx = threadIdx.x, ty = threadIdx.y;
    int k0 = blockIdx.y * 32, n0 = blockIdx.x * 32;
#pragma unroll
    for (int i = 0; i < 4; i++) {
        int kk = ty * 4 + i;
        t[kk][tx] = W[(size_t)(k0 + kk) * DD + n0 + tx];
    }
    __syncthreads();
#pragma unroll
    for (int i = 0; i < 4; i++) {
        int n = n0 + ty * 4 + i;
        int k = k0 + tx;
        float v = t[tx][ty * 4 + i];
        __nv_bfloat16 hi = __float2bfloat16(v);
        __nv_bfloat16 lo = __float2bfloat16(v - __bfloat162float(hi));
        __nv_bfloat16* row = O + (size_t)n * KTOT;
        row[k] = hi; row[2048 + k] = hi; row[1024 + k] = lo;
    }
}

// ---------------------------------------------------------------------------
// mma.sync bf16 GEMM: C[4096,1024] over K=3072. 128x128 CTA, 8 warps.
// MODE 0: A=g_xs, B=g_ws[z]; epilogue splits into g_qx/g_kx/g_vx (bf16 hi/lo)
// MODE 1: A=g_zs, B=g_ws[3]; epilogue = Cout + bias (fp32)
// ---------------------------------------------------------------------------
#define GBK 32
#define NCH (KTOT / GBK)   // 96
#define PAD 40

template<int MODE>
__global__ __launch_bounds__(256)
void mma_gemm(const float* __restrict__ bias, float* __restrict__ Cout) {
    __shared__ __align__(16) __nv_bfloat16 sA[2][128][PAD];
    __shared__ __align__(16) __nv_bfloat16 sB[2][128][PAD];

    const int tid = threadIdx.x;
    const int wid = tid >> 5, lane = tid & 31;
    const int wm = wid >> 2;
    const int wn = wid & 3;

    const __nv_bfloat16* A = (MODE == 0) ? g_xs : g_zs;
    const __nv_bfloat16* B = (MODE == 0) ? g_ws[blockIdx.z] : g_ws[3];
    const __nv_bfloat16* Ab = A + (size_t)blockIdx.y * 128 * KTOT;
    const __nv_bfloat16* Bb = B + (size_t)blockIdx.x * 128 * KTOT;

    const uint32_t sAu = smem_u32(&sA[0][0][0]);
    const uint32_t sBu = smem_u32(&sB[0][0][0]);
    const uint32_t stageB = 128 * PAD * 2;

    const int lr0 = tid >> 2, lc = (tid & 3) * 8;
    const int lr1 = (tid + 256) >> 2;

    float acc[4][4][4];
#pragma unroll
    for (int i = 0; i < 4; i++)
#pragma unroll
        for (int j = 0; j < 4; j++)
#pragma unroll
            for (int v = 0; v < 4; v++) acc[i][j][v] = 0.f;

    auto load_chunk = [&](int chunk, int s) {
        const __nv_bfloat16* Ak = Ab + (size_t)chunk * GBK;
        const __nv_bfloat16* Bk = Bb + (size_t)chunk * GBK;
        cp16(sAu + s * stageB + (lr0 * PAD + lc) * 2, Ak + (size_t)lr0 * KTOT + lc);
        cp16(sAu + s * stageB + (lr1 * PAD + lc) * 2, Ak + (size_t)lr1 * KTOT + lc);
        cp16(sBu + s * stageB + (lr0 * PAD + lc) * 2, Bk + (size_t)lr0 * KTOT + lc);
        cp16(sBu + s * stageB + (lr1 * PAD + lc) * 2, Bk + (size_t)lr1 * KTOT + lc);
    };

    load_chunk(0, 0);
    asm volatile("cp.async.commit_group;");

    for (int i = 0; i < NCH; i++) {
        const int s = i & 1;
        if (i + 1 < NCH) {
            load_chunk(i + 1, (i + 1) & 1);
            asm volatile("cp.async.commit_group;");
            asm volatile("cp.async.wait_group 1;");
        } else {
            asm volatile("cp.async.wait_group 0;");
        }
        __syncthreads();

#pragma unroll
        for (int k0 = 0; k0 < GBK; k0 += 16) {
            uint32_t afr[4][4];
#pragma unroll
            for (int mi = 0; mi < 4; mi++) {
                int row = wm * 64 + mi * 16 + (lane & 15);
                int col = k0 + (lane >> 4) * 8;
                ldsm_x4(afr[mi], sAu + s * stageB + (row * PAD + col) * 2);
            }
            uint32_t bfr[4][2];
#pragma unroll
            for (int ni = 0; ni < 4; ni++) {
                int l = lane & 15;
                int row = wn * 32 + ni * 8 + (l & 7);
                int col = k0 + (l >> 3) * 8;
                ldsm_x2(bfr[ni], sBu + s * stageB + (row * PAD + col) * 2);
            }
#pragma unroll
            for (int mi = 0; mi < 4; mi++)
#pragma unroll
                for (int ni = 0; ni < 4; ni++)
                    mma_bf16(acc[mi][ni], afr[mi], bfr[ni][0], bfr[ni][1]);
        }
        __syncthreads();
    }

    // Epilogue
    const int qr = lane >> 2, qc = (lane & 3) * 2;
#pragma unroll
    for (int mi = 0; mi < 4; mi++) {
#pragma unroll
        for (int ni = 0; ni < 4; ni++) {
            int col  = blockIdx.x * 128 + wn * 32 + ni * 8 + qc;
            int row0 = blockIdx.y * 128 + wm * 64 + mi * 16 + qr;
            int row1 = row0 + 8;
            float v0 = acc[mi][ni][0], v1 = acc[mi][ni][1];
            float v2 = acc[mi][ni][2], v3 = acc[mi][ni][3];
            if (MODE == 0) {
                const int z = blockIdx.z;
                if (z == 0) { v0 *= 0.125f; v1 *= 0.125f; v2 *= 0.125f; v3 *= 0.125f; }
                int h = col >> 6, hd = col & 63;
                int b0 = row0 >> 11, s0 = row0 & (SS - 1);
                int b1 = row1 >> 11, s1 = row1 & (SS - 1);
                int bh0 = b0 * NH + h, bh1 = b1 * NH + h;
                uint32_t H01 = bfpack(v0, v1), L01 = bfpack(bfres(v0), bfres(v1));
                uint32_t H23 = bfpack(v2, v3), L23 = bfpack(bfres(v2), bfres(v3));
                if (z == 0) {
                    __nv_bfloat16* p0 = g_qx + ((size_t)bh0 * SS + s0) * 192 + hd;
                    __nv_bfloat16* p1 = g_qx + ((size_t)bh1 * SS + s1) * 192 + hd;
                    *(uint32_t*)p0 = H01; *(uint32_t*)(p0 + 64) = H01; *(uint32_t*)(p0 + 128) = L01;
                    *(uint32_t*)p1 = H23; *(uint32_t*)(p1 + 64) = H23; *(uint32_t*)(p1 + 128) = L23;
                } else if (z == 1) {
                    __nv_bfloat16* p0 = g_kx + ((size_t)bh0 * SS + s0) * 192 + hd;
                    __nv_bfloat16* p1 = g_kx + ((size_t)bh1 * SS + s1) * 192 + hd;
                    *(uint32_t*)p0 = H01; *(uint32_t*)(p0 + 64) = L01; *(uint32_t*)(p0 + 128) = H01;
                    *(uint32_t*)p1 = H23; *(uint32_t*)(p1 + 64) = L23; *(uint32_t*)(p1 + 128) = H23;
                } else {
                    __nv_bfloat16* p0 = g_vx + ((size_t)bh0 * 3 * SS + s0) * HD + hd;
                    __nv_bfloat16* p1 = g_vx + ((size_t)bh1 * 3 * SS + s1) * HD + hd;
                    *(uint32_t*)p0 = H01; *(uint32_t*)(p0 + SS * HD) = L01; *(uint32_t*)(p0 + 2 * SS * HD) = H01;
                    *(uint32_t*)p1 = H23; *(uint32_t*)(p1 + SS * HD) = L23; *(uint32_t*)(p1 + 2 * SS * HD) = H23;
                }
            } else {
                float bx0 = bias[col], bx1 = bias[col + 1];
                *(float2*)(Cout + (size_t)row0 * DD + col) = make_float2(v0 + bx0, v1 + bx1);
                *(float2*)(Cout + (size_t)row1 * DD + col) = make_float2(v2 + bx0, v3 + bx1);
            }
        }
    }
}

// ---------------------------------------------------------------------------
// Flash attention on mma.sync. 64 q-rows/CTA, 4 warps (warp = 16 rows).
// QK over K'=192 (hi/lo), PV over 192 (P hi/lo x V hi/lo). exp on FMA pipe.
// smem: Kbuf [64][200] bf16 (25600 B), Vbuf [192][72] bf16 (27648 B).
// ---------------------------------------------------------------------------
#define KSTR 400           // bytes per K/Q smem row
#define VSTR 144           // bytes per V smem row
#define FSMEM (25600 + 27648)

__global__ __launch_bounds__(128)
void flash_mma() {
    extern __shared__ __align__(16) char fs[];
    const uint32_t kb = smem_u32(fs);
    const uint32_t vb = kb + 25600;
    const int tid = threadIdx.x, w = tid >> 5, lane = tid & 31;
    const int qb = gridDim.x - 1 - blockIdx.x;    // heavy CTAs first
    const int bh = blockIdx.y;

    const __nv_bfloat16* Qg = g_qx + ((size_t)bh * SS + qb * 64) * 192;
    const __nv_bfloat16* Kg = g_kx + (size_t)bh * SS * 192;
    const __nv_bfloat16* Vg = g_vx + (size_t)bh * 3 * SS * HD;

    // ldmatrix per-lane offsets
    const int ra = lane & 15, ca = (lane >> 4) << 3;               // A (rows of Q)
    const int rb = (lane & 7) + ((lane >> 1) & 8), cb = lane & 8;  // B for QK (rows of K)
    const int rv = lane & 15, cv = (lane >> 4) << 3;               // B for PV (trans)

    // ---- Q into Kbuf, extract a-frags ----
    uint32_t qfr[12][4];
#pragma unroll
    for (int t = 0; t < 12; t++) {
        int idx = tid + t * 128;
        int r = idx / 24, c = idx - r * 24;
        cp16(kb + r * KSTR + c * 16, Qg + (size_t)r * 192 + c * 8);
    }
    asm volatile("cp.async.commit_group;");
    asm volatile("cp.async.wait_group 0;");
    __syncthreads();
#pragma unroll
    for (int k = 0; k < 12; k++)
        ldsm_x4(qfr[k], kb + (16 * w + ra) * KSTR + (k * 16 + ca) * 2);

    float m0 = -1e30f, m1 = -1e30f, l0 = 0.f, l1 = 0.f;
    float o[8][4];
#pragma unroll
    for (int j = 0; j < 8; j++)
#pragma unroll
        for (int v = 0; v < 4; v++) o[j][v] = 0.f;

    for (int kt = 0; kt <= qb; kt++) {
        __syncthreads();   // Kbuf/Vbuf free for reuse
#pragma unroll
        for (int t = 0; t < 12; t++) {
            int idx = tid + t * 128;
            int r = idx / 24, c = idx - r * 24;
            cp16(kb + r * KSTR + c * 16, Kg + (size_t)(kt * 64 + r) * 192 + c * 8);
        }
#pragma unroll
        for (int t = 0; t < 12; t++) {
            int idx = tid + t * 128;
            int r = idx >> 3, c = idx & 7;       // r in 0..191
            int seg = r >> 6, rr = r & 63;
            cp16(vb + r * VSTR + c * 16, Vg + (size_t)(seg * SS + kt * 64 + rr) * HD + c * 8);
        }
        asm volatile("cp.async.commit_group;");
        asm volatile("cp.async.wait_group 0;");
        __syncthreads();

        // ---- S = Q K'^T ----
        float sf[8][4];
#pragma unroll
        for (int j = 0; j < 8; j++)
#pragma unroll
            for (int v = 0; v < 4; v++) sf[j][v] = 0.f;
#pragma unroll
        for (int jj = 0; jj < 4; jj++) {
#pragma unroll
            for (int k = 0; k < 12; k++) {
                uint32_t r4[4];
                ldsm_x4(r4, kb + (16 * jj + rb) * KSTR + (k * 16 + cb) * 2);
                mma_bf16(sf[2 * jj],     qfr[k], r4[0], r4[1]);
                mma_bf16(sf[2 * jj + 1], qfr[k], r4[2], r4[3]);
            }
        }

        // ---- causal mask on diagonal tile ----
        if (kt == qb) {
            int row0 = 16 * w + (lane >> 2);
#pragma unroll
            for (int j = 0; j < 8; j++) {
                int key = 8 * j + 2 * (lane & 3);
                if (key     > row0)     sf[j][0] = -1e30f;
                if (key + 1 > row0)     sf[j][1] = -1e30f;
                if (key     > row0 + 8) sf[j][2] = -1e30f;
                if (key + 1 > row0 + 8) sf[j][3] = -1e30f;
            }
        }

        // ---- online softmax ----
        float tm0 = -1e30f, tm1 = -1e30f;
#pragma unroll
        for (int j = 0; j < 8; j++) {
            tm0 = fmaxf(tm0, fmaxf(sf[j][0], sf[j][1]));
            tm1 = fmaxf(tm1, fmaxf(sf[j][2], sf[j][3]));
        }
        tm0 = fmaxf(tm0, __shfl_xor_sync(0xffffffffu, tm0, 1));
        tm0 = fmaxf(tm0, __shfl_xor_sync(0xffffffffu, tm0, 2));
        tm1 = fmaxf(tm1, __shfl_xor_sync(0xffffffffu, tm1, 1));
        tm1 = fmaxf(tm1, __shfl_xor_sync(0xffffffffu, tm1, 2));
        float mn0 = fmaxf(m0, tm0), mn1 = fmaxf(m1, tm1);
        float c0 = fexp(m0 - mn0), c1 = fexp(m1 - mn1);
        m0 = mn0; m1 = mn1;

        float s0 = 0.f, s1 = 0.f;
        uint32_t ph[4][4], pl[4][4];
#pragma unroll
        for (int t = 0; t < 4; t++) {
            float pa = fexp(sf[2 * t][0] - mn0),     pb = fexp(sf[2 * t][1] - mn0);
            float pc = fexp(sf[2 * t][2] - mn1),     pd = fexp(sf[2 * t][3] - mn1);
            float pe = fexp(sf[2 * t + 1][0] - mn0), pf = fexp(sf[2 * t + 1][1] - mn0);
            float pg = fexp(sf[2 * t + 1][2] - mn1), pq = fexp(sf[2 * t + 1][3] - mn1);
            s0 += (pa + pb) + (pe + pf);
            s1 += (pc + pd) + (pg + pq);
            ph[t][0] = bfpack(pa, pb); pl[t][0] = bfpack(bfres(pa), bfres(pb));
            ph[t][1] = bfpack(pc, pd); pl[t][1] = bfpack(bfres(pc), bfres(pd));
            ph[t][2] = bfpack(pe, pf); pl[t][2] = bfpack(bfres(pe), bfres(pf));
            ph[t][3] = bfpack(pg, pq); pl[t][3] = bfpack(bfres(pg), bfres(pq));
        }
        s0 += __shfl_xor_sync(0xffffffffu, s0, 1);
        s0 += __shfl_xor_sync(0xffffffffu, s0, 2);
        s1 += __shfl_xor_sync(0xffffffffu, s1, 1);
        s1 += __shfl_xor_sync(0xffffffffu, s1, 2);
        l0 = l0 * c0 + s0;
        l1 = l1 * c1 + s1;
#pragma unroll
        for (int j = 0; j < 8; j++) {
            o[j][0] *= c0; o[j][1] *= c0; o[j][2] *= c1; o[j][3] *= c1;
        }

        // ---- O += P' V' ----
#pragma unroll
        for (int kc = 0; kc < 12; kc++) {
            const uint32_t* Af = (kc < 8) ? ph[kc & 3] : pl[kc & 3];
            uint32_t a4[4] = {Af[0], Af[1], Af[2], Af[3]};
#pragma unroll
            for (int jj = 0; jj < 4; jj++) {
                uint32_t r4[4];
                ldsm_x4t(r4, vb + (kc * 16 + rv) * VSTR + (jj * 16 + cv) * 2);
                mma_bf16(o[2 * jj],     a4, r4[0], r4[1]);
                mma_bf16(o[2 * jj + 1], a4, r4[2], r4[3]);
            }
        }
    }

    // ---- epilogue: write z split directly into g_zs ----
    float i0 = 1.f / l0, i1 = 1.f / l1;
    int b = bh >> 4, h = bh & 15;
    int srow = qb * 64 + 16 * w + (lane >> 2);
    __nv_bfloat16* z0 = g_zs + (size_t)(b * SS + srow) * KTOT;
    __nv_bfloat16* z1 = g_zs + (size_t)(b * SS + srow + 8) * KTOT;
    int kk = h * 64 + 2 * (lane & 3);
#pragma unroll
    for (int j = 0; j < 8; j++) {
        int col = kk + 8 * j;
        float v0 = o[j][0] * i0, v1 = o[j][1] * i0;
        float v2 = o[j][2] * i1, v3 = o[j][3] * i1;
        uint32_t H0 = bfpack(v0, v1), L0 = bfpack(bfres(v0), bfres(v1));
        uint32_t H1 = bfpack(v2, v3), L1 = bfpack(bfres(v2), bfres(v3));
        *(uint32_t*)(z0 + col) = H0; *(uint32_t*)(z0 + 1024 + col) = H0; *(uint32_t*)(z0 + 2048 + col) = L0;
        *(uint32_t*)(z1 + col) = H1; *(uint32_t*)(z1 + 1024 + col) = H1; *(uint32_t*)(z1 + 2048 + col) = L1;
    }
}

// ---------------------------------------------------------------------------
extern "C" void kernel_launch(void* const* d_in, const int* in_sizes, int n_in,
                              void* d_out, int out_size)
{
    const float* x  = (const float*)d_in[0];
    const float* Wq = (const float*)d_in[1];
    const float* Wk = (const float*)d_in[2];
    const float* Wv = (const float*)d_in[3];
    const float* Wo = (const float*)d_in[4];
    const float* bo = (const float*)d_in[5];
    float* out = (float*)d_out;

    cudaFuncSetAttribute(flash_mma, cudaFuncAttributeMaxDynamicSharedMemorySize, FSMEM);

    conv_split<<<(size_t)MM * DD / 256, 256>>>(x);
    conv_w<<<dim3(32, 32, 4), dim3(32, 8)>>>(Wq, Wk, Wv, Wo);

    mma_gemm<0><<<dim3(8, 32, 3), 256>>>(nullptr, nullptr);

    flash_mma<<<dim3(SS / 64, NB * NH), 128, FSMEM>>>();

    mma_gemm<1><<<dim3(8, 32, 1), 256>>>(bo, out);
}

// round 12
// speedup vs baseline: 2.3306x; 1.0783x over previous
#include <cuda_runtime.h>
#include <cuda_bf16.h>
#include <cstdint>

#define NB 2
#define SS 2048
#define DD 1024
#define NH 16
#define HD 64
#define MM (NB*SS)
#define KTOT 3072   // 3x K-expansion for bf16 hi/lo compensation

// ---------------------------------------------------------------------------
// Scratch (__device__ globals; allocation-free rule)
// ---------------------------------------------------------------------------
__device__ __nv_bfloat16 g_xs[(size_t)MM*KTOT];        // x split-expanded [M][3K]
__device__ __nv_bfloat16 g_zs[(size_t)MM*KTOT];        // z split-expanded [M][3K]
__device__ __nv_bfloat16 g_ws[4][(size_t)DD*KTOT];     // W transposed+split [N][3K]
__device__ __nv_bfloat16 g_qx[(size_t)NB*NH*SS*192];   // Q [bh][s][qh|qh|ql], pre-scaled 1/8
__device__ __nv_bfloat16 g_kx[(size_t)NB*NH*SS*192];   // K [bh][s][kh|kl|kh]
__device__ __nv_bfloat16 g_vx[(size_t)NB*NH*3*SS*HD];  // V [bh][vh rows | vl rows | vh rows][hd]

// ---------------------------------------------------------------------------
// Helpers (sm_100-safe PTX: cp.async / ldmatrix / mma.sync)
// ---------------------------------------------------------------------------
__device__ __forceinline__ uint32_t smem_u32(const void* p) {
    uint32_t a;
    asm("{ .reg .u64 t; cvta.to.shared.u64 t, %1; cvt.u32.u64 %0, t; }" : "=r"(a) : "l"(p));
    return a;
}
__device__ __forceinline__ void cp16(uint32_t s, const void* g) {
    asm volatile("cp.async.cg.shared.global [%0], [%1], 16;" :: "r"(s), "l"(g));
}
__device__ __forceinline__ void ldsm_x4(uint32_t (&r)[4], uint32_t a) {
    asm volatile("ldmatrix.sync.aligned.m8n8.x4.shared.b16 {%0,%1,%2,%3}, [%4];"
                 : "=r"(r[0]), "=r"(r[1]), "=r"(r[2]), "=r"(r[3]) : "r"(a));
}
__device__ __forceinline__ void ldsm_x4t(uint32_t (&r)[4], uint32_t a) {
    asm volatile("ldmatrix.sync.aligned.m8n8.x4.trans.shared.b16 {%0,%1,%2,%3}, [%4];"
                 : "=r"(r[0]), "=r"(r[1]), "=r"(r[2]), "=r"(r[3]) : "r"(a));
}
__device__ __forceinline__ void ldsm_x2(uint32_t (&r)[2], uint32_t a) {
    asm volatile("ldmatrix.sync.aligned.m8n8.x2.shared.b16 {%0,%1}, [%2];"
                 : "=r"(r[0]), "=r"(r[1]) : "r"(a));
}
__device__ __forceinline__ void mma_bf16(float (&c)[4], const uint32_t (&a)[4],
                                         uint32_t b0, uint32_t b1) {
    asm volatile("mma.sync.aligned.m16n8k16.row.col.f32.bf16.bf16.f32 "
                 "{%0,%1,%2,%3}, {%4,%5,%6,%7}, {%8,%9}, {%0,%1,%2,%3};"
                 : "+f"(c[0]), "+f"(c[1]), "+f"(c[2]), "+f"(c[3])
                 : "r"(a[0]), "r"(a[1]), "r"(a[2]), "r"(a[3]), "r"(b0), "r"(b1));
}
__device__ __forceinline__ uint32_t bfpack(float a, float b) {
    __nv_bfloat162 t = __floats2bfloat162_rn(a, b);
    return *reinterpret_cast<uint32_t*>(&t);
}
__device__ __forceinline__ float bfres(float a) {
    return a - __bfloat162float(__float2bfloat16(a));
}
// exp on the FMA/ALU pipes (no MUFU). Valid for x <= 0; flushes to ~0 below -87.
__device__ __forceinline__ float fexp(float x) {
    float y = x * 1.4426950408889634f;
    y = fmaxf(y, -126.0f);
    float t = y + 12582912.0f;            // round-to-nearest-int (magic)
    int   i = __float_as_int(t);
    float f = y - (t - 12582912.0f);      // frac in [-0.5, 0.5]
    float p = fmaf(f, 1.3333558146e-3f, 9.6181291076e-3f);
    p = fmaf(f, p, 5.5504108664e-2f);
    p = fmaf(f, p, 2.4022650696e-1f);
    p = fmaf(f, p, 6.9314718056e-1f);
    p = fmaf(f, p, 1.0f);
    return p * __int_as_float((i + 127) << 23);
}

// ---------------------------------------------------------------------------
// Conversions
// ---------------------------------------------------------------------------
__global__ void conv_split(const float* __restrict__ xin) {
    size_t idx = (size_t)blockIdx.x * 256 + threadIdx.x;
    int m = (int)(idx >> 10), kk = (int)(idx & 1023);
    float v = xin[idx];
    __nv_bfloat16 hi = __float2bfloat16(v);
    __nv_bfloat16 lo = __float2bfloat16(v - __bfloat162float(hi));
    __nv_bfloat16* row = g_xs + (size_t)m * KTOT;
    row[kk] = hi; row[1024 + kk] = hi; row[2048 + kk] = lo;
}

// W[K,N] -> g_ws[z][N][3K]: seg0 = hi, seg1 = lo, seg2 = hi
__global__ void conv_w(const float* __restrict__ W0, const float* __restrict__ W1,
                       const float* __restrict__ W2, const float* __restrict__ W3) {
    __shared__ float t[32][33];
    const int z = blockIdx.z;
    const float* W = (z == 0) ? W0 : (z == 1) ? W1 : (z == 2) ? W2 : W3;
    __nv_bfloat16* O = g_ws[z];
    int tx = threadIdx.x, ty = threadIdx.y;
    int k0 = blockIdx.y * 32, n0 = blockIdx.x * 32;
#pragma unroll
    for (int i = 0; i < 4; i++) {
        int kk = ty * 4 + i;
        t[kk][tx] = W[(size_t)(k0 + kk) * DD + n0 + tx];
    }
    __syncthreads();
#pragma unroll
    for (int i = 0; i < 4; i++) {
        int n = n0 + ty * 4 + i;
        int k = k0 + tx;
        float v = t[tx][ty * 4 + i];
        __nv_bfloat16 hi = __float2bfloat16(v);
        __nv_bfloat16 lo = __float2bfloat16(v - __bfloat162float(hi));
        __nv_bfloat16* row = O + (size_t)n * KTOT;
        row[k] = hi; row[2048 + k] = hi; row[1024 + k] = lo;
    }
}

// ---------------------------------------------------------------------------
// mma.sync bf16 GEMM: C[4096,1024] over K=3072. 128x128 CTA, 8 warps.
// K-chunk 64, 2-stage cp.async pipeline, dynamic smem (rows padded to 72 bf16).
// MODE 0: A=g_xs, B=g_ws[z]; epilogue splits into g_qx/g_kx/g_vx (bf16 hi/lo)
// MODE 1: A=g_zs, B=g_ws[3]; epilogue = Cout + bias (fp32)
// ---------------------------------------------------------------------------
#define GBK 64
#define NCH (KTOT / GBK)        // 48
#define GPAD 72                 // elements per smem row (144 B)
#define GSTG (128 * GPAD * 2)   // bytes per stage per matrix = 18432
#define GSMEM (4 * GSTG)        // 73728

template<int MODE>
__global__ __launch_bounds__(256)
void mma_gemm(const float* __restrict__ bias, float* __restrict__ Cout) {
    extern __shared__ __align__(16) char gs[];
    const uint32_t sAu = smem_u32(gs);
    const uint32_t sBu = sAu + 2 * GSTG;

    const int tid = threadIdx.x;
    const int wid = tid >> 5, lane = tid & 31;
    const int wm = wid >> 2;
    const int wn = wid & 3;

    const __nv_bfloat16* A = (MODE == 0) ? g_xs : g_zs;
    const __nv_bfloat16* B = (MODE == 0) ? g_ws[blockIdx.z] : g_ws[3];
    const __nv_bfloat16* Ab = A + (size_t)blockIdx.y * 128 * KTOT;
    const __nv_bfloat16* Bb = B + (size_t)blockIdx.x * 128 * KTOT;

    const int lr = tid >> 3;            // 0..31 (+32 per t)
    const int lce = (tid & 7) * 8;      // element col
    const int lcb = lce * 2;            // byte col

    float acc[4][4][4];
#pragma unroll
    for (int i = 0; i < 4; i++)
#pragma unroll
        for (int j = 0; j < 4; j++)
#pragma unroll
            for (int v = 0; v < 4; v++) acc[i][j][v] = 0.f;

    auto load_chunk = [&](int chunk, int s) {
        const __nv_bfloat16* Ak = Ab + (size_t)chunk * GBK;
        const __nv_bfloat16* Bk = Bb + (size_t)chunk * GBK;
#pragma unroll
        for (int t = 0; t < 4; t++) {
            int row = lr + t * 32;
            cp16(sAu + s * GSTG + row * (GPAD * 2) + lcb, Ak + (size_t)row * KTOT + lce);
            cp16(sBu + s * GSTG + row * (GPAD * 2) + lcb, Bk + (size_t)row * KTOT + lce);
        }
    };

    load_chunk(0, 0);
    asm volatile("cp.async.commit_group;");

    for (int i = 0; i < NCH; i++) {
        const int s = i & 1;
        if (i + 1 < NCH) {
            load_chunk(i + 1, (i + 1) & 1);
            asm volatile("cp.async.commit_group;");
            asm volatile("cp.async.wait_group 1;");
        } else {
            asm volatile("cp.async.wait_group 0;");
        }
        __syncthreads();

#pragma unroll
        for (int k0 = 0; k0 < GBK; k0 += 16) {
            uint32_t afr[4][4];
#pragma unroll
            for (int mi = 0; mi < 4; mi++) {
                int row = wm * 64 + mi * 16 + (lane & 15);
                int col = k0 + (lane >> 4) * 8;
                ldsm_x4(afr[mi], sAu + s * GSTG + (row * GPAD + col) * 2);
            }
            uint32_t bfr[4][2];
#pragma unroll
            for (int ni = 0; ni < 4; ni++) {
                int l = lane & 15;
                int row = wn * 32 + ni * 8 + (l & 7);
                int col = k0 + (l >> 3) * 8;
                ldsm_x2(bfr[ni], sBu + s * GSTG + (row * GPAD + col) * 2);
            }
#pragma unroll
            for (int mi = 0; mi < 4; mi++)
#pragma unroll
                for (int ni = 0; ni < 4; ni++)
                    mma_bf16(acc[mi][ni], afr[mi], bfr[ni][0], bfr[ni][1]);
        }
        __syncthreads();
    }

    // Epilogue
    const int qr = lane >> 2, qc = (lane & 3) * 2;
#pragma unroll
    for (int mi = 0; mi < 4; mi++) {
#pragma unroll
        for (int ni = 0; ni < 4; ni++) {
            int col  = blockIdx.x * 128 + wn * 32 + ni * 8 + qc;
            int row0 = blockIdx.y * 128 + wm * 64 + mi * 16 + qr;
            int row1 = row0 + 8;
            float v0 = acc[mi][ni][0], v1 = acc[mi][ni][1];
            float v2 = acc[mi][ni][2], v3 = acc[mi][ni][3];
            if (MODE == 0) {
                const int z = blockIdx.z;
                if (z == 0) { v0 *= 0.125f; v1 *= 0.125f; v2 *= 0.125f; v3 *= 0.125f; }
                int h = col >> 6, hd = col & 63;
                int b0 = row0 >> 11, s0 = row0 & (SS - 1);
                int b1 = row1 >> 11, s1 = row1 & (SS - 1);
                int bh0 = b0 * NH + h, bh1 = b1 * NH + h;
                uint32_t H01 = bfpack(v0, v1), L01 = bfpack(bfres(v0), bfres(v1));
                uint32_t H23 = bfpack(v2, v3), L23 = bfpack(bfres(v2), bfres(v3));
                if (z == 0) {
                    __nv_bfloat16* p0 = g_qx + ((size_t)bh0 * SS + s0) * 192 + hd;
                    __nv_bfloat16* p1 = g_qx + ((size_t)bh1 * SS + s1) * 192 + hd;
                    *(uint32_t*)p0 = H01; *(uint32_t*)(p0 + 64) = H01; *(uint32_t*)(p0 + 128) = L01;
                    *(uint32_t*)p1 = H23; *(uint32_t*)(p1 + 64) = H23; *(uint32_t*)(p1 + 128) = L23;
                } else if (z == 1) {
                    __nv_bfloat16* p0 = g_kx + ((size_t)bh0 * SS + s0) * 192 + hd;
                    __nv_bfloat16* p1 = g_kx + ((size_t)bh1 * SS + s1) * 192 + hd;
                    *(uint32_t*)p0 = H01; *(uint32_t*)(p0 + 64) = L01; *(uint32_t*)(p0 + 128) = H01;
                    *(uint32_t*)p1 = H23; *(uint32_t*)(p1 + 64) = L23; *(uint32_t*)(p1 + 128) = H23;
                } else {
                    __nv_bfloat16* p0 = g_vx + ((size_t)bh0 * 3 * SS + s0) * HD + hd;
                    __nv_bfloat16* p1 = g_vx + ((size_t)bh1 * 3 * SS + s1) * HD + hd;
                    *(uint32_t*)p0 = H01; *(uint32_t*)(p0 + SS * HD) = L01; *(uint32_t*)(p0 + 2 * SS * HD) = H01;
                    *(uint32_t*)p1 = H23; *(uint32_t*)(p1 + SS * HD) = L23; *(uint32_t*)(p1 + 2 * SS * HD) = H23;
                }
            } else {
                float bx0 = bias[col], bx1 = bias[col + 1];
                *(float2*)(Cout + (size_t)row0 * DD + col) = make_float2(v0 + bx0, v1 + bx1);
                *(float2*)(Cout + (size_t)row1 * DD + col) = make_float2(v2 + bx0, v3 + bx1);
            }
        }
    }
}

// ---------------------------------------------------------------------------
// Flash attention on mma.sync. 64 q-rows/CTA, 4 warps (warp = 16 rows).
// QK over K'=192 (hi/lo), PV over 192 (P hi/lo x V hi/lo). exp on FMA pipe.
// 2-stage cp.async pipeline on K/V.
// smem: K 2x[64][200] bf16 (2x25600 B), V 2x[192][72] bf16 (2x27648 B).
// ---------------------------------------------------------------------------
#define KSTR 400           // bytes per K/Q smem row
#define VSTR 144           // bytes per V smem row
#define KSTG 25600
#define VSTG 27648
#define FSMEM (2 * KSTG + 2 * VSTG)   // 106496

__global__ __launch_bounds__(128, 2)
void flash_mma() {
    extern __shared__ __align__(16) char fs[];
    const uint32_t kb = smem_u32(fs);          // 2 K stages
    const uint32_t vb = kb + 2 * KSTG;         // 2 V stages
    const int tid = threadIdx.x, w = tid >> 5, lane = tid & 31;
    const int qb = gridDim.x - 1 - blockIdx.x;    // heavy CTAs first
    const int bh = blockIdx.y;

    const __nv_bfloat16* Qg = g_qx + ((size_t)bh * SS + qb * 64) * 192;
    const __nv_bfloat16* Kg = g_kx + (size_t)bh * SS * 192;
    const __nv_bfloat16* Vg = g_vx + (size_t)bh * 3 * SS * HD;

    // ldmatrix per-lane offsets
    const int ra = lane & 15, ca = (lane >> 4) << 3;               // A (rows of Q)
    const int rb = (lane & 7) + ((lane >> 1) & 8), cb = lane & 8;  // B for QK (rows of K)
    const int rv = lane & 15, cv = (lane >> 4) << 3;               // B for PV (trans)

    // ---- Q into K stage 0, extract a-frags ----
    uint32_t qfr[12][4];
#pragma unroll
    for (int t = 0; t < 12; t++) {
        int idx = tid + t * 128;
        int r = idx / 24, c = idx - r * 24;
        cp16(kb + r * KSTR + c * 16, Qg + (size_t)r * 192 + c * 8);
    }
    asm volatile("cp.async.commit_group;");
    asm volatile("cp.async.wait_group 0;");
    __syncthreads();
#pragma unroll
    for (int k = 0; k < 12; k++)
        ldsm_x4(qfr[k], kb + (16 * w + ra) * KSTR + (k * 16 + ca) * 2);
    __syncthreads();   // everyone has Q frags; K stage 0 reusable

    auto load_kv = [&](int kt, int s) {
#pragma unroll
        for (int t = 0; t < 12; t++) {
            int idx = tid + t * 128;
            int r = idx / 24, c = idx - r * 24;
            cp16(kb + s * KSTG + r * KSTR + c * 16, Kg + (size_t)(kt * 64 + r) * 192 + c * 8);
        }
#pragma unroll
        for (int t = 0; t < 12; t++) {
            int idx = tid + t * 128;
            int r = idx >> 3, c = idx & 7;       // r in 0..191
            int seg = r >> 6, rr = r & 63;
            cp16(vb + s * VSTG + r * VSTR + c * 16, Vg + (size_t)(seg * SS + kt * 64 + rr) * HD + c * 8);
        }
    };

    float m0 = -1e30f, m1 = -1e30f, l0 = 0.f, l1 = 0.f;
    float o[8][4];
#pragma unroll
    for (int j = 0; j < 8; j++)
#pragma unroll
        for (int v = 0; v < 4; v++) o[j][v] = 0.f;

    load_kv(0, 0);
    asm volatile("cp.async.commit_group;");

    for (int kt = 0; kt <= qb; kt++) {
        const int s = kt & 1;
        if (kt < qb) {
            load_kv(kt + 1, s ^ 1);
            asm volatile("cp.async.commit_group;");
            asm volatile("cp.async.wait_group 1;");
        } else {
            asm volatile("cp.async.wait_group 0;");
        }
        __syncthreads();
        const uint32_t kbs = kb + s * KSTG;
        const uint32_t vbs = vb + s * VSTG;

        // ---- S = Q K'^T ----
        float sf[8][4];
#pragma unroll
        for (int j = 0; j < 8; j++)
#pragma unroll
            for (int v = 0; v < 4; v++) sf[j][v] = 0.f;
#pragma unroll
        for (int jj = 0; jj < 4; jj++) {
#pragma unroll
            for (int k = 0; k < 12; k++) {
                uint32_t r4[4];
                ldsm_x4(r4, kbs + (16 * jj + rb) * KSTR + (k * 16 + cb) * 2);
                mma_bf16(sf[2 * jj],     qfr[k], r4[0], r4[1]);
                mma_bf16(sf[2 * jj + 1], qfr[k], r4[2], r4[3]);
            }
        }

        // ---- causal mask on diagonal tile ----
        if (kt == qb) {
            int row0 = 16 * w + (lane >> 2);
#pragma unroll
            for (int j = 0; j < 8; j++) {
                int key = 8 * j + 2 * (lane & 3);
                if (key     > row0)     sf[j][0] = -1e30f;
                if (key + 1 > row0)     sf[j][1] = -1e30f;
                if (key     > row0 + 8) sf[j][2] = -1e30f;
                if (key + 1 > row0 + 8) sf[j][3] = -1e30f;
            }
        }

        // ---- online softmax ----
        float tm0 = -1e30f, tm1 = -1e30f;
#pragma unroll
        for (int j = 0; j < 8; j++) {
            tm0 = fmaxf(tm0, fmaxf(sf[j][0], sf[j][1]));
            tm1 = fmaxf(tm1, fmaxf(sf[j][2], sf[j][3]));
        }
        tm0 = fmaxf(tm0, __shfl_xor_sync(0xffffffffu, tm0, 1));
        tm0 = fmaxf(tm0, __shfl_xor_sync(0xffffffffu, tm0, 2));
        tm1 = fmaxf(tm1, __shfl_xor_sync(0xffffffffu, tm1, 1));
        tm1 = fmaxf(tm1, __shfl_xor_sync(0xffffffffu, tm1, 2));
        float mn0 = fmaxf(m0, tm0), mn1 = fmaxf(m1, tm1);
        float c0 = fexp(m0 - mn0), c1 = fexp(m1 - mn1);
        m0 = mn0; m1 = mn1;

        float s0 = 0.f, s1 = 0.f;
        uint32_t ph[4][4], pl[4][4];
#pragma unroll
        for (int t = 0; t < 4; t++) {
            float pa = fexp(sf[2 * t][0] - mn0),     pb = fexp(sf[2 * t][1] - mn0);
            float pc = fexp(sf[2 * t][2] - mn1),     pd = fexp(sf[2 * t][3] - mn1);
            float pe = fexp(sf[2 * t + 1][0] - mn0), pf = fexp(sf[2 * t + 1][1] - mn0);
            float pg = fexp(sf[2 * t + 1][2] - mn1), pq = fexp(sf[2 * t + 1][3] - mn1);
            s0 += (pa + pb) + (pe + pf);
            s1 += (pc + pd) + (pg + pq);
            ph[t][0] = bfpack(pa, pb); pl[t][0] = bfpack(bfres(pa), bfres(pb));
            ph[t][1] = bfpack(pc, pd); pl[t][1] = bfpack(bfres(pc), bfres(pd));
            ph[t][2] = bfpack(pe, pf); pl[t][2] = bfpack(bfres(pe), bfres(pf));
            ph[t][3] = bfpack(pg, pq); pl[t][3] = bfpack(bfres(pg), bfres(pq));
        }
        s0 += __shfl_xor_sync(0xffffffffu, s0, 1);
        s0 += __shfl_xor_sync(0xffffffffu, s0, 2);
        s1 += __shfl_xor_sync(0xffffffffu, s1, 1);
        s1 += __shfl_xor_sync(0xffffffffu, s1, 2);
        l0 = l0 * c0 + s0;
        l1 = l1 * c1 + s1;
#pragma unroll
        for (int j = 0; j < 8; j++) {
            o[j][0] *= c0; o[j][1] *= c0; o[j][2] *= c1; o[j][3] *= c1;
        }

        // ---- O += P' V' ----
#pragma unroll
        for (int kc = 0; kc < 12; kc++) {
            const uint32_t* Af = (kc < 8) ? ph[kc & 3] : pl[kc & 3];
            uint32_t a4[4] = {Af[0], Af[1], Af[2], Af[3]};
#pragma unroll
            for (int jj = 0; jj < 4; jj++) {
                uint32_t r4[4];
                ldsm_x4t(r4, vbs + (kc * 16 + rv) * VSTR + (jj * 16 + cv) * 2);
                mma_bf16(o[2 * jj],     a4, r4[0], r4[1]);
                mma_bf16(o[2 * jj + 1], a4, r4[2], r4[3]);
            }
        }
        __syncthreads();   // stage s consumed; safe for next-next load
    }

    // ---- epilogue: write z split directly into g_zs ----
    float i0 = 1.f / l0, i1 = 1.f / l1;
    int b = bh >> 4, h = bh & 15;
    int srow = qb * 64 + 16 * w + (lane >> 2);
    __nv_bfloat16* z0 = g_zs + (size_t)(b * SS + srow) * KTOT;
    __nv_bfloat16* z1 = g_zs + (size_t)(b * SS + srow + 8) * KTOT;
    int kk = h * 64 + 2 * (lane & 3);
#pragma unroll
    for (int j = 0; j < 8; j++) {
        int col = kk + 8 * j;
        float v0 = o[j][0] * i0, v1 = o[j][1] * i0;
        float v2 = o[j][2] * i1, v3 = o[j][3] * i1;
        uint32_t H0 = bfpack(v0, v1), L0 = bfpack(bfres(v0), bfres(v1));
        uint32_t H1 = bfpack(v2, v3), L1 = bfpack(bfres(v2), bfres(v3));
        *(uint32_t*)(z0 + col) = H0; *(uint32_t*)(z0 + 1024 + col) = H0; *(uint32_t*)(z0 + 2048 + col) = L0;
        *(uint32_t*)(z1 + col) = H1; *(uint32_t*)(z1 + 1024 + col) = H1; *(uint32_t*)(z1 + 2048 + col) = L1;
    }
}

// ---------------------------------------------------------------------------
extern "C" void kernel_launch(void* const* d_in, const int* in_sizes, int n_in,
                              void* d_out, int out_size)
{
    const float* x  = (const float*)d_in[0];
    const float* Wq = (const float*)d_in[1];
    const float* Wk = (const float*)d_in[2];
    const float* Wv = (const float*)d_in[3];
    const float* Wo = (const float*)d_in[4];
    const float* bo = (const float*)d_in[5];
    float* out = (float*)d_out;

    cudaFuncSetAttribute(flash_mma, cudaFuncAttributeMaxDynamicSharedMemorySize, FSMEM);
    cudaFuncSetAttribute(mma_gemm<0>, cudaFuncAttributeMaxDynamicSharedMemorySize, GSMEM);
    cudaFuncSetAttribute(mma_gemm<1>, cudaFuncAttributeMaxDynamicSharedMemorySize, GSMEM);

    conv_split<<<(size_t)MM * DD / 256, 256>>>(x);
    conv_w<<<dim3(32, 32, 4), dim3(32, 8)>>>(Wq, Wk, Wv, Wo);

    mma_gemm<0><<<dim3(8, 32, 3), 256, GSMEM>>>(nullptr, nullptr);

    flash_mma<<<dim3(SS / 64, NB * NH), 128, FSMEM>>>();

    mma_gemm<1><<<dim3(8, 32, 1), 256, GSMEM>>>(bo, out);
}